// round 2
// baseline (speedup 1.0000x reference)
#include <cuda_runtime.h>

#define E_EDGES 1600000
#define NN 100000
#define HID 64
#define BN_EPS 1e-5f
#define INV_E (1.0f/1600000.0f)

typedef unsigned long long ull;

__device__ __forceinline__ ull pack2(float lo, float hi){
  ull r; asm("mov.b64 %0,{%1,%2};" : "=l"(r) : "f"(lo), "f"(hi)); return r;
}
__device__ __forceinline__ void unpack2(ull v, float &lo, float &hi){
  asm("mov.b64 {%0,%1},%2;" : "=f"(lo), "=f"(hi) : "l"(v));
}
__device__ __forceinline__ ull fma2(ull a, ull b, ull c){
  ull d; asm("fma.rn.f32x2 %0,%1,%2,%3;" : "=l"(d) : "l"(a), "l"(b), "l"(c)); return d;
}

// ---------------- scratch (device globals; no allocations allowed) ----------------
__device__ float d_h1[(size_t)E_EDGES*HID];   // h1, later reused for h3
__device__ float d_h2[(size_t)E_EDGES*HID];
__device__ int d_src[E_EDGES], d_dst[E_EDGES];
__device__ float d_sum0[HID], d_sq0[HID];
__device__ float d_sum1[HID], d_sq1[HID];
__device__ float d_sum2[HID], d_sq2[HID];
__device__ float d_normsq;
__device__ int d_is64;
__device__ float d_W2f[HID*HID], d_b2f[HID];
__device__ float d_W3f[HID*HID], d_b3f[HID];
__device__ float d_a3[HID], d_c3[HID];
__device__ int d_cnt[NN], d_off[NN+1], d_cur[NN], d_csr[E_EDGES];

// ---------------- init: zero counters / stats (must re-run every graph replay) ----
__global__ void k_init(){
  int i = blockIdx.x*blockDim.x + threadIdx.x;
  int stride = gridDim.x*blockDim.x;
  for (int j=i; j<NN; j+=stride) d_cnt[j]=0;
  if (i < HID){
    d_sum0[i]=0.f; d_sq0[i]=0.f;
    d_sum1[i]=0.f; d_sq1[i]=0.f;
    d_sum2[i]=0.f; d_sq2[i]=0.f;
  }
  if (i==0){ d_normsq = 0.f; d_is64 = 1; }
}

// ---------------- dtype probe: int64 vs int32 edge_index ---------------------------
// Reads the first 1M entries interpreted as int64 (2M int32 words — safe in both
// layouts). Any value outside [0, NN) means the data is really int32.
__global__ void k_detect(const long long* __restrict__ ei){
  int tid = blockIdx.x*blockDim.x + threadIdx.x;
  int bad = 0;
  #pragma unroll 4
  for (int i = tid; i < (1<<20); i += gridDim.x*blockDim.x){
    long long v = ei[i];
    if (v < 0 || v >= NN) bad = 1;
  }
  if (__syncthreads_or(bad)){
    if (threadIdx.x == 0) d_is64 = 0;
  }
}

// ---------------- convert indices + global norm + dst histogram --------------------
__global__ void k_cvt_norm_hist(const void* __restrict__ eiv, const float* __restrict__ pos){
  const long long* ei64 = (const long long*)eiv;
  const int*       ei32 = (const int*)eiv;
  const bool is64 = (d_is64 != 0);
  int tid = blockIdx.x*blockDim.x + threadIdx.x;
  int stride = gridDim.x*blockDim.x;
  float local = 0.f;
  for (int e = tid; e < E_EDGES; e += stride){
    int s, d;
    if (is64){ s = (int)ei64[e]; d = (int)ei64[E_EDGES + e]; }
    else     { s = ei32[e];      d = ei32[E_EDGES + e]; }
    d_src[e] = s; d_dst[e] = d;
    float dx = pos[3*s+0] - pos[3*d+0];
    float dy = pos[3*s+1] - pos[3*d+1];
    float dz = pos[3*s+2] - pos[3*d+2];
    local += dx*dx + dy*dy + dz*dz;
    atomicAdd(&d_cnt[d], 1);
  }
  #pragma unroll
  for (int o=16;o>0;o>>=1) local += __shfl_down_sync(0xffffffffu, local, o);
  __shared__ float red[8];
  int lane = threadIdx.x & 31, wid = threadIdx.x >> 5;
  if (lane==0) red[wid]=local;
  __syncthreads();
  if (threadIdx.x==0){
    float s=0.f;
    #pragma unroll
    for (int i=0;i<8;i++) s+=red[i];
    atomicAdd(&d_normsq, s);
  }
}

// ---------------- exclusive prefix sum over counts (1 block) ----------------------
__global__ void k_scan(){
  __shared__ int wsum[32];
  __shared__ int sh_carry;
  const int t = threadIdx.x;
  const int lane = t & 31, wid = t >> 5;
  if (t==0) sh_carry = 0;
  __syncthreads();
  for (int base=0; base<NN; base+=4096){
    int carry = sh_carry;
    int idx = base + t*4;
    int v0 = (idx+0<NN)? d_cnt[idx+0] : 0;
    int v1 = (idx+1<NN)? d_cnt[idx+1] : 0;
    int v2 = (idx+2<NN)? d_cnt[idx+2] : 0;
    int v3 = (idx+3<NN)? d_cnt[idx+3] : 0;
    int s1=v0+v1, s2=s1+v2, s3=s2+v3;
    int x = s3;
    #pragma unroll
    for (int o=1;o<32;o<<=1){ int y=__shfl_up_sync(0xffffffffu,x,o); if(lane>=o) x+=y; }
    if (lane==31) wsum[wid]=x;
    __syncthreads();
    if (wid==0){
      int y = wsum[lane];
      #pragma unroll
      for (int o=1;o<32;o<<=1){ int z=__shfl_up_sync(0xffffffffu,y,o); if(lane>=o) y+=z; }
      wsum[lane]=y;
    }
    __syncthreads();
    int woff = (wid>0)? wsum[wid-1] : 0;
    int texcl = carry + woff + (x - s3);
    if (idx+0<NN){ d_off[idx+0]=texcl;    d_cur[idx+0]=texcl;    }
    if (idx+1<NN){ d_off[idx+1]=texcl+v0; d_cur[idx+1]=texcl+v0; }
    if (idx+2<NN){ d_off[idx+2]=texcl+s1; d_cur[idx+2]=texcl+s1; }
    if (idx+3<NN){ d_off[idx+3]=texcl+s2; d_cur[idx+3]=texcl+s2; }
    int total = wsum[31];
    __syncthreads();
    if (t==0) sh_carry = carry + total;
    __syncthreads();
  }
  if (t==0) d_off[NN] = sh_carry;
}

// ---------------- CSR fill --------------------------------------------------------
__global__ void k_scatter(){
  int tid = blockIdx.x*blockDim.x + threadIdx.x;
  int stride = gridDim.x*blockDim.x;
  for (int e=tid; e<E_EDGES; e+=stride){
    int d = d_dst[e];
    int p = atomicAdd(&d_cur[d], 1);
    d_csr[p] = e;
  }
}

// ---------------- layer 1: 6 -> 64, per-edge, lane = channel pair ------------------
__global__ void k_layer1(const float* __restrict__ pos,
                         const float* __restrict__ x, const float* __restrict__ W1,
                         const float* __restrict__ b1){
  int lane = threadIdx.x & 31;
  int gw = (blockIdx.x*blockDim.x + threadIdx.x) >> 5;
  int nw = (gridDim.x*blockDim.x) >> 5;
  float invn = rsqrtf(d_normsq);
  ull wp[6];
  #pragma unroll
  for (int k=0;k<6;k++){
    float2 w = ((const float2*)(W1 + k*HID))[lane];
    wp[k] = pack2(w.x, w.y);
  }
  float2 bb = ((const float2*)b1)[lane];
  ull bias = pack2(bb.x, bb.y);
  float sx=0.f, sy=0.f, qx=0.f, qy=0.f;
  for (int e=gw; e<E_EDGES; e+=nw){
    int s = d_src[e];
    int d = d_dst[e];
    float i0 = (pos[3*s+0]-pos[3*d+0])*invn;
    float i1 = (pos[3*s+1]-pos[3*d+1])*invn;
    float i2 = (pos[3*s+2]-pos[3*d+2])*invn;
    float i3 = x[3*d+0], i4 = x[3*d+1], i5 = x[3*d+2];
    ull acc = bias;
    acc = fma2(pack2(i0,i0), wp[0], acc);
    acc = fma2(pack2(i1,i1), wp[1], acc);
    acc = fma2(pack2(i2,i2), wp[2], acc);
    acc = fma2(pack2(i3,i3), wp[3], acc);
    acc = fma2(pack2(i4,i4), wp[4], acc);
    acc = fma2(pack2(i5,i5), wp[5], acc);
    float h0, h1v; unpack2(acc, h0, h1v);
    h0 = fmaxf(h0, 0.f); h1v = fmaxf(h1v, 0.f);
    ((float2*)(d_h1 + (size_t)e*HID))[lane] = make_float2(h0, h1v);
    sx += h0; sy += h1v; qx += h0*h0; qy += h1v*h1v;
  }
  atomicAdd(&d_sum0[2*lane+0], sx);
  atomicAdd(&d_sum0[2*lane+1], sy);
  atomicAdd(&d_sq0 [2*lane+0], qx);
  atomicAdd(&d_sq0 [2*lane+1], qy);
}

// ---------------- fold BN(prev layer) into next layer's weights -------------------
__global__ void k_fold(const float* __restrict__ W, const float* __restrict__ b,
                       const float* __restrict__ g, const float* __restrict__ be, int which){
  __shared__ float a[HID], c[HID];
  int t = threadIdx.x;
  const float* sum = (which==0) ? d_sum0 : d_sum1;
  const float* sq  = (which==0) ? d_sq0  : d_sq1;
  float* Wf = (which==0) ? d_W2f : d_W3f;
  float* bf = (which==0) ? d_b2f : d_b3f;
  float mu = sum[t]*INV_E;
  float var = sq[t]*INV_E - mu*mu;
  float av = g[t]*rsqrtf(var + BN_EPS);
  a[t] = av; c[t] = be[t] - av*mu;
  __syncthreads();
  float cb = 0.f;
  for (int k=0;k<HID;k++){
    float w = W[k*HID + t];
    Wf[k*HID + t] = a[k]*w;
    cb += c[k]*w;
  }
  bf[t] = b[t] + cb;
}

__global__ void k_affine3(const float* __restrict__ g, const float* __restrict__ be){
  int t = threadIdx.x;
  float mu = d_sum2[t]*INV_E;
  float var = d_sq2[t]*INV_E - mu*mu;
  float av = g[t]*rsqrtf(var + BN_EPS);
  d_a3[t] = av; d_c3[t] = be[t] - av*mu;
}

// ---------------- layer 2/3: 64x64 GEMM + relu + stats, f32x2 packed FMA -----------
__global__ void __launch_bounds__(256) k_layer(int which){
  const float* __restrict__ hin  = (which==0) ? d_h1 : d_h2;
  float* __restrict__ hout       = (which==0) ? d_h2 : d_h1;
  const float* __restrict__ Wf   = (which==0) ? d_W2f : d_W3f;
  const float* __restrict__ bf   = (which==0) ? d_b2f : d_b3f;
  float* gs = (which==0) ? d_sum1 : d_sum2;
  float* gq = (which==0) ? d_sq1  : d_sq2;

  __shared__ float Ash[128][65];
  __shared__ float Wsh[64][64];
  __shared__ float bsh[64];
  __shared__ float ssum[64], ssq[64];

  int t = threadIdx.x;
  size_t e0 = (size_t)blockIdx.x * 128;

  {
    const float4* W4 = (const float4*)Wf;
    float4* Wd = (float4*)&Wsh[0][0];
    #pragma unroll
    for (int i=0;i<4;i++) Wd[t + 256*i] = W4[t + 256*i];
  }
  if (t < 64){ bsh[t] = bf[t]; ssum[t]=0.f; ssq[t]=0.f; }
  {
    const float4* h4 = (const float4*)(hin + e0*HID);
    #pragma unroll
    for (int i=0;i<8;i++){
      int idx = t + 256*i;
      float4 v = h4[idx];
      int e = idx >> 4;
      int k4 = (idx & 15) << 2;
      Ash[e][k4+0]=v.x; Ash[e][k4+1]=v.y; Ash[e][k4+2]=v.z; Ash[e][k4+3]=v.w;
    }
  }
  __syncthreads();

  int cg = t & 7;        // channel group (8 channels = 4 pairs)
  int eg = t >> 3;       // edge group (4 edges)
  int ebase = eg << 2;
  int cbase = cg << 3;

  ull acc[4][4];
  {
    ull b0 = pack2(bsh[cbase+0], bsh[cbase+1]);
    ull b1v= pack2(bsh[cbase+2], bsh[cbase+3]);
    ull b2v= pack2(bsh[cbase+4], bsh[cbase+5]);
    ull b3v= pack2(bsh[cbase+6], bsh[cbase+7]);
    #pragma unroll
    for (int i=0;i<4;i++){ acc[i][0]=b0; acc[i][1]=b1v; acc[i][2]=b2v; acc[i][3]=b3v; }
  }

  #pragma unroll 8
  for (int k=0;k<64;k++){
    const ull* wr = (const ull*)&Wsh[k][cbase];
    ull w0=wr[0], w1=wr[1], w2=wr[2], w3=wr[3];
    #pragma unroll
    for (int i=0;i<4;i++){
      float a = Ash[ebase+i][k];
      ull aa = pack2(a,a);
      acc[i][0] = fma2(aa, w0, acc[i][0]);
      acc[i][1] = fma2(aa, w1, acc[i][1]);
      acc[i][2] = fma2(aa, w2, acc[i][2]);
      acc[i][3] = fma2(aa, w3, acc[i][3]);
    }
  }

  float2 s[4], q[4];
  #pragma unroll
  for (int j=0;j<4;j++){ s[j]=make_float2(0.f,0.f); q[j]=make_float2(0.f,0.f); }

  #pragma unroll
  for (int i=0;i<4;i++){
    float v[8];
    unpack2(acc[i][0], v[0], v[1]);
    unpack2(acc[i][1], v[2], v[3]);
    unpack2(acc[i][2], v[4], v[5]);
    unpack2(acc[i][3], v[6], v[7]);
    #pragma unroll
    for (int m=0;m<8;m++) v[m] = fmaxf(v[m], 0.f);
    float* outp = hout + (e0 + (size_t)(ebase + i))*HID + cbase;
    ((float4*)outp)[0] = make_float4(v[0],v[1],v[2],v[3]);
    ((float4*)outp)[1] = make_float4(v[4],v[5],v[6],v[7]);
    #pragma unroll
    for (int j=0;j<4;j++){
      s[j].x += v[2*j]; s[j].y += v[2*j+1];
      q[j].x += v[2*j]*v[2*j]; q[j].y += v[2*j+1]*v[2*j+1];
    }
  }

  #pragma unroll
  for (int j=0;j<4;j++){
    atomicAdd(&ssum[cbase+2*j+0], s[j].x);
    atomicAdd(&ssum[cbase+2*j+1], s[j].y);
    atomicAdd(&ssq [cbase+2*j+0], q[j].x);
    atomicAdd(&ssq [cbase+2*j+1], q[j].y);
  }
  __syncthreads();
  if (t < 64){
    atomicAdd(&gs[t], ssum[t]);
    atomicAdd(&gq[t], ssq[t]);
  }
}

// ---------------- per-node gather max + BN3 affine ---------------------------------
__global__ void k_gather(float* __restrict__ out){
  int lane = threadIdx.x & 31;
  int node = (blockIdx.x*blockDim.x + threadIdx.x) >> 5;
  if (node >= NN) return;
  int beg = d_off[node], end = d_off[node+1];
  float mx = -3.402823466e38f, my = -3.402823466e38f;
  for (int base=beg; base<end; base+=32){
    int p = base + lane;
    int eL = (p < end) ? d_csr[p] : 0;
    int cnt = min(32, end - base);
    for (int j=0;j<cnt;j++){
      int e = __shfl_sync(0xffffffffu, eL, j);
      float2 v = ((const float2*)(d_h1 + (size_t)e*HID))[lane];
      mx = fmaxf(mx, v.x); my = fmaxf(my, v.y);
    }
  }
  float rx, ry;
  if (end > beg){
    rx = d_a3[2*lane+0]*mx + d_c3[2*lane+0];
    ry = d_a3[2*lane+1]*my + d_c3[2*lane+1];
  } else { rx = 0.f; ry = 0.f; }
  ((float2*)(out + (size_t)node*HID))[lane] = make_float2(rx, ry);
}

// ---------------- launch ------------------------------------------------------------
extern "C" void kernel_launch(void* const* d_in, const int* in_sizes, int n_in,
                              void* d_out, int out_size){
  const float*     x   = (const float*)d_in[0];
  const float*     pos = (const float*)d_in[1];
  const void*      ei  = d_in[2];
  const float* W1=(const float*)d_in[3];  const float* b1=(const float*)d_in[4];
  const float* g1=(const float*)d_in[5];  const float* be1=(const float*)d_in[6];
  const float* W2=(const float*)d_in[7];  const float* b2=(const float*)d_in[8];
  const float* g2=(const float*)d_in[9];  const float* be2=(const float*)d_in[10];
  const float* W3=(const float*)d_in[11]; const float* b3=(const float*)d_in[12];
  const float* g3=(const float*)d_in[13]; const float* be3=(const float*)d_in[14];
  float* out = (float*)d_out;
  (void)in_sizes; (void)n_in; (void)out_size;

  k_init<<<128,256>>>();
  k_detect<<<1024,256>>>((const long long*)ei);
  k_cvt_norm_hist<<<1600,256>>>(ei, pos);
  k_scan<<<1,1024>>>();
  k_scatter<<<1600,256>>>();
  k_layer1<<<1600,256>>>(pos, x, W1, b1);
  k_fold<<<1,64>>>(W2, b2, g1, be1, 0);
  k_layer<<<12500,256>>>(0);
  k_fold<<<1,64>>>(W3, b3, g2, be2, 1);
  k_layer<<<12500,256>>>(1);
  k_affine3<<<1,64>>>(g3, be3);
  k_gather<<<12500,256>>>(out);
}

// round 3
// speedup vs baseline: 1.1388x; 1.1388x over previous
#include <cuda_runtime.h>
#include <cuda_fp16.h>

#define E_EDGES 1600000
#define NN 100000
#define HID 64
#define BN_EPS 1e-5f
#define INV_E (1.0f/1600000.0f)
#define NBLK 98   // ceil(NN/1024)

typedef unsigned long long ull;

__device__ __forceinline__ ull pack2(float lo, float hi){
  ull r; asm("mov.b64 %0,{%1,%2};" : "=l"(r) : "f"(lo), "f"(hi)); return r;
}
__device__ __forceinline__ void unpack2(ull v, float &lo, float &hi){
  asm("mov.b64 {%0,%1},%2;" : "=f"(lo), "=f"(hi) : "l"(v));
}
__device__ __forceinline__ ull fma2(ull a, ull b, ull c){
  ull d; asm("fma.rn.f32x2 %0,%1,%2,%3;" : "=l"(d) : "l"(a), "l"(b), "l"(c)); return d;
}

// ---------------- scratch (device globals; no allocations allowed) ----------------
__device__ __half d_h1[(size_t)E_EDGES*HID];   // h1, later reused for h3
__device__ __half d_h2[(size_t)E_EDGES*HID];
__device__ int d_src[E_EDGES], d_dst[E_EDGES];
__device__ float d_sum0[HID], d_sq0[HID];
__device__ float d_sum1[HID], d_sq1[HID];
__device__ float d_sum2[HID], d_sq2[HID];
__device__ float d_normsq;
__device__ int d_is64;
__device__ float d_W2f[HID*HID], d_b2f[HID];
__device__ float d_W3f[HID*HID], d_b3f[HID];
__device__ float d_a3[HID], d_c3[HID];
__device__ int d_cnt[NN], d_off[NN+1], d_cur[NN], d_csr[E_EDGES];
__device__ int d_blk[128];

// ---------------- init: zero counters / stats (must re-run every graph replay) ----
__global__ void k_init(){
  int i = blockIdx.x*blockDim.x + threadIdx.x;
  int stride = gridDim.x*blockDim.x;
  for (int j=i; j<NN; j+=stride) d_cnt[j]=0;
  if (i < HID){
    d_sum0[i]=0.f; d_sq0[i]=0.f;
    d_sum1[i]=0.f; d_sq1[i]=0.f;
    d_sum2[i]=0.f; d_sq2[i]=0.f;
  }
  if (i==0){ d_normsq = 0.f; d_is64 = 1; }
}

// ---------------- dtype probe: int64 vs int32 edge_index ---------------------------
__global__ void k_detect(const long long* __restrict__ ei){
  int tid = blockIdx.x*blockDim.x + threadIdx.x;
  int bad = 0;
  #pragma unroll 4
  for (int i = tid; i < (1<<20); i += gridDim.x*blockDim.x){
    long long v = ei[i];
    if (v < 0 || v >= NN) bad = 1;
  }
  if (__syncthreads_or(bad)){
    if (threadIdx.x == 0) d_is64 = 0;
  }
}

// ---------------- convert indices + global norm + dst histogram --------------------
__global__ void k_cvt_norm_hist(const void* __restrict__ eiv, const float* __restrict__ pos){
  const long long* ei64 = (const long long*)eiv;
  const int*       ei32 = (const int*)eiv;
  const bool is64 = (d_is64 != 0);
  int tid = blockIdx.x*blockDim.x + threadIdx.x;
  int stride = gridDim.x*blockDim.x;
  float local = 0.f;
  for (int e = tid; e < E_EDGES; e += stride){
    int s, d;
    if (is64){ s = (int)ei64[e]; d = (int)ei64[E_EDGES + e]; }
    else     { s = ei32[e];      d = ei32[E_EDGES + e]; }
    d_src[e] = s; d_dst[e] = d;
    float dx = pos[3*s+0] - pos[3*d+0];
    float dy = pos[3*s+1] - pos[3*d+1];
    float dz = pos[3*s+2] - pos[3*d+2];
    local += dx*dx + dy*dy + dz*dz;
    atomicAdd(&d_cnt[d], 1);
  }
  #pragma unroll
  for (int o=16;o>0;o>>=1) local += __shfl_down_sync(0xffffffffu, local, o);
  __shared__ float red[8];
  int lane = threadIdx.x & 31, wid = threadIdx.x >> 5;
  if (lane==0) red[wid]=local;
  __syncthreads();
  if (threadIdx.x==0){
    float s=0.f;
    #pragma unroll
    for (int i=0;i<8;i++) s+=red[i];
    atomicAdd(&d_normsq, s);
  }
}

// ---------------- parallel 3-phase exclusive scan ----------------------------------
__global__ void k_scan1(){
  __shared__ int wsum[32];
  int t = threadIdx.x, lane = t & 31, wid = t >> 5;
  int idx = blockIdx.x*1024 + t;
  int v = (idx < NN) ? d_cnt[idx] : 0;
  int x = v;
  #pragma unroll
  for (int o=1;o<32;o<<=1){ int y=__shfl_up_sync(0xffffffffu,x,o); if(lane>=o) x+=y; }
  if (lane==31) wsum[wid]=x;
  __syncthreads();
  if (wid==0){
    int y = wsum[lane];
    #pragma unroll
    for (int o=1;o<32;o<<=1){ int z=__shfl_up_sync(0xffffffffu,y,o); if(lane>=o) y+=z; }
    wsum[lane]=y;
  }
  __syncthreads();
  int excl = x - v + ((wid>0)? wsum[wid-1] : 0);
  if (idx < NN) d_off[idx] = excl;
  if (t==1023) d_blk[blockIdx.x] = wsum[31];
}

__global__ void k_scan2(){
  __shared__ int wsum[4];
  int t = threadIdx.x, lane = t & 31, wid = t >> 5;   // 128 threads
  int v = (t < NBLK) ? d_blk[t] : 0;
  int x = v;
  #pragma unroll
  for (int o=1;o<32;o<<=1){ int y=__shfl_up_sync(0xffffffffu,x,o); if(lane>=o) x+=y; }
  if (lane==31) wsum[wid]=x;
  __syncthreads();
  int woff = 0;
  for (int w=0; w<wid; w++) woff += wsum[w];
  if (t < NBLK) d_blk[t] = x - v + woff;
}

__global__ void k_scan3(){
  int idx = blockIdx.x*1024 + threadIdx.x;
  if (idx < NN){
    int o = d_off[idx] + d_blk[blockIdx.x];
    d_off[idx] = o; d_cur[idx] = o;
  }
  if (idx == 0) d_off[NN] = E_EDGES;
}

// ---------------- CSR fill --------------------------------------------------------
__global__ void k_scatter(){
  int tid = blockIdx.x*blockDim.x + threadIdx.x;
  int stride = gridDim.x*blockDim.x;
  for (int e=tid; e<E_EDGES; e+=stride){
    int d = d_dst[e];
    int p = atomicAdd(&d_cur[d], 1);
    d_csr[p] = e;
  }
}

// ---------------- layer 1: 6 -> 64, per-edge, lane = channel pair ------------------
__global__ void k_layer1(const float* __restrict__ pos,
                         const float* __restrict__ x, const float* __restrict__ W1,
                         const float* __restrict__ b1){
  int lane = threadIdx.x & 31;
  int gw = (blockIdx.x*blockDim.x + threadIdx.x) >> 5;
  int nw = (gridDim.x*blockDim.x) >> 5;
  float invn = rsqrtf(d_normsq);
  ull wp[6];
  #pragma unroll
  for (int k=0;k<6;k++){
    float2 w = ((const float2*)(W1 + k*HID))[lane];
    wp[k] = pack2(w.x, w.y);
  }
  float2 bb = ((const float2*)b1)[lane];
  ull bias = pack2(bb.x, bb.y);
  float sx=0.f, sy=0.f, qx=0.f, qy=0.f;
  for (int e=gw; e<E_EDGES; e+=nw){
    int s = d_src[e];
    int d = d_dst[e];
    float i0 = (pos[3*s+0]-pos[3*d+0])*invn;
    float i1 = (pos[3*s+1]-pos[3*d+1])*invn;
    float i2 = (pos[3*s+2]-pos[3*d+2])*invn;
    float i3 = x[3*d+0], i4 = x[3*d+1], i5 = x[3*d+2];
    ull acc = bias;
    acc = fma2(pack2(i0,i0), wp[0], acc);
    acc = fma2(pack2(i1,i1), wp[1], acc);
    acc = fma2(pack2(i2,i2), wp[2], acc);
    acc = fma2(pack2(i3,i3), wp[3], acc);
    acc = fma2(pack2(i4,i4), wp[4], acc);
    acc = fma2(pack2(i5,i5), wp[5], acc);
    float h0, h1v; unpack2(acc, h0, h1v);
    h0 = fmaxf(h0, 0.f); h1v = fmaxf(h1v, 0.f);
    ((__half2*)(d_h1 + (size_t)e*HID))[lane] = __floats2half2_rn(h0, h1v);
    sx += h0; sy += h1v; qx += h0*h0; qy += h1v*h1v;
  }
  atomicAdd(&d_sum0[2*lane+0], sx);
  atomicAdd(&d_sum0[2*lane+1], sy);
  atomicAdd(&d_sq0 [2*lane+0], qx);
  atomicAdd(&d_sq0 [2*lane+1], qy);
}

// ---------------- fold BN(prev layer) into next layer's weights -------------------
__global__ void k_fold(const float* __restrict__ W, const float* __restrict__ b,
                       const float* __restrict__ g, const float* __restrict__ be, int which){
  __shared__ float a[HID], c[HID];
  int t = threadIdx.x;
  const float* sum = (which==0) ? d_sum0 : d_sum1;
  const float* sq  = (which==0) ? d_sq0  : d_sq1;
  float* Wf = (which==0) ? d_W2f : d_W3f;
  float* bf = (which==0) ? d_b2f : d_b3f;
  float mu = sum[t]*INV_E;
  float var = sq[t]*INV_E - mu*mu;
  float av = g[t]*rsqrtf(var + BN_EPS);
  a[t] = av; c[t] = be[t] - av*mu;
  __syncthreads();
  float cb = 0.f;
  for (int k=0;k<HID;k++){
    float w = W[k*HID + t];
    Wf[k*HID + t] = a[k]*w;
    cb += c[k]*w;
  }
  bf[t] = b[t] + cb;
}

__global__ void k_affine3(const float* __restrict__ g, const float* __restrict__ be){
  int t = threadIdx.x;
  float mu = d_sum2[t]*INV_E;
  float var = d_sq2[t]*INV_E - mu*mu;
  float av = g[t]*rsqrtf(var + BN_EPS);
  d_a3[t] = av; d_c3[t] = be[t] - av*mu;
}

// ---------------- layer 2/3: 64x64 GEMM + relu + stats, f32x2 packed FMA -----------
__global__ void __launch_bounds__(256) k_layer(int which){
  const __half* __restrict__ hin = (which==0) ? d_h1 : d_h2;
  __half* __restrict__ hout      = (which==0) ? d_h2 : d_h1;
  const float* __restrict__ Wf   = (which==0) ? d_W2f : d_W3f;
  const float* __restrict__ bf   = (which==0) ? d_b2f : d_b3f;
  float* gs = (which==0) ? d_sum1 : d_sum2;
  float* gq = (which==0) ? d_sq1  : d_sq2;

  __shared__ float Ash[128][65];
  __shared__ float Wsh[64][64];
  __shared__ float bsh[64];
  __shared__ float ssum[64], ssq[64];

  int t = threadIdx.x;
  size_t e0 = (size_t)blockIdx.x * 128;

  {
    const float4* W4 = (const float4*)Wf;
    float4* Wd = (float4*)&Wsh[0][0];
    #pragma unroll
    for (int i=0;i<4;i++) Wd[t + 256*i] = W4[t + 256*i];
  }
  if (t < 64){ bsh[t] = bf[t]; ssum[t]=0.f; ssq[t]=0.f; }
  {
    // 128 edges x 64 ch halves = 16KB = 1024 uint4; thread handles 4
    const uint4* h4 = (const uint4*)(hin + e0*HID);
    #pragma unroll
    for (int i=0;i<4;i++){
      int idx = t + 256*i;           // uint4 index; edge = idx>>3, chunk = idx&7
      uint4 v = h4[idx];
      int e = idx >> 3;
      int c8 = (idx & 7) << 3;
      const __half2* hp = (const __half2*)&v;
      #pragma unroll
      for (int j=0;j<4;j++){
        float2 f = __half22float2(hp[j]);
        Ash[e][c8 + 2*j + 0] = f.x;
        Ash[e][c8 + 2*j + 1] = f.y;
      }
    }
  }
  __syncthreads();

  int cg = t & 7;        // channel group (8 channels = 4 pairs)
  int eg = t >> 3;       // edge group (4 edges)
  int ebase = eg << 2;
  int cbase = cg << 3;

  ull acc[4][4];
  {
    ull b0 = pack2(bsh[cbase+0], bsh[cbase+1]);
    ull b1v= pack2(bsh[cbase+2], bsh[cbase+3]);
    ull b2v= pack2(bsh[cbase+4], bsh[cbase+5]);
    ull b3v= pack2(bsh[cbase+6], bsh[cbase+7]);
    #pragma unroll
    for (int i=0;i<4;i++){ acc[i][0]=b0; acc[i][1]=b1v; acc[i][2]=b2v; acc[i][3]=b3v; }
  }

  #pragma unroll 8
  for (int k=0;k<64;k++){
    const ull* wr = (const ull*)&Wsh[k][cbase];
    ull w0=wr[0], w1=wr[1], w2=wr[2], w3=wr[3];
    #pragma unroll
    for (int i=0;i<4;i++){
      float a = Ash[ebase+i][k];
      ull aa = pack2(a,a);
      acc[i][0] = fma2(aa, w0, acc[i][0]);
      acc[i][1] = fma2(aa, w1, acc[i][1]);
      acc[i][2] = fma2(aa, w2, acc[i][2]);
      acc[i][3] = fma2(aa, w3, acc[i][3]);
    }
  }

  float2 s[4], q[4];
  #pragma unroll
  for (int j=0;j<4;j++){ s[j]=make_float2(0.f,0.f); q[j]=make_float2(0.f,0.f); }

  #pragma unroll
  for (int i=0;i<4;i++){
    float v[8];
    unpack2(acc[i][0], v[0], v[1]);
    unpack2(acc[i][1], v[2], v[3]);
    unpack2(acc[i][2], v[4], v[5]);
    unpack2(acc[i][3], v[6], v[7]);
    #pragma unroll
    for (int m=0;m<8;m++) v[m] = fmaxf(v[m], 0.f);
    // pack 8 halves = uint4, store 16B
    uint4 ov;
    __half2* op = (__half2*)&ov;
    op[0] = __floats2half2_rn(v[0], v[1]);
    op[1] = __floats2half2_rn(v[2], v[3]);
    op[2] = __floats2half2_rn(v[4], v[5]);
    op[3] = __floats2half2_rn(v[6], v[7]);
    *(uint4*)(hout + (e0 + (size_t)(ebase + i))*HID + cbase) = ov;
    #pragma unroll
    for (int j=0;j<4;j++){
      s[j].x += v[2*j]; s[j].y += v[2*j+1];
      q[j].x += v[2*j]*v[2*j]; q[j].y += v[2*j+1]*v[2*j+1];
    }
  }

  #pragma unroll
  for (int j=0;j<4;j++){
    atomicAdd(&ssum[cbase+2*j+0], s[j].x);
    atomicAdd(&ssum[cbase+2*j+1], s[j].y);
    atomicAdd(&ssq [cbase+2*j+0], q[j].x);
    atomicAdd(&ssq [cbase+2*j+1], q[j].y);
  }
  __syncthreads();
  if (t < 64){
    atomicAdd(&gs[t], ssum[t]);
    atomicAdd(&gq[t], ssq[t]);
  }
}

// ---------------- per-node gather max + BN3 affine ---------------------------------
__global__ void k_gather(float* __restrict__ out){
  int lane = threadIdx.x & 31;
  int node = (blockIdx.x*blockDim.x + threadIdx.x) >> 5;
  if (node >= NN) return;
  int beg = d_off[node], end = d_off[node+1];
  float mx = -3.402823466e38f, my = -3.402823466e38f;
  for (int base=beg; base<end; base+=32){
    int p = base + lane;
    int eL = (p < end) ? d_csr[p] : 0;
    int cnt = min(32, end - base);
    for (int j=0;j<cnt;j++){
      int e = __shfl_sync(0xffffffffu, eL, j);
      float2 v = __half22float2(((const __half2*)(d_h1 + (size_t)e*HID))[lane]);
      mx = fmaxf(mx, v.x); my = fmaxf(my, v.y);
    }
  }
  float rx, ry;
  if (end > beg){
    rx = d_a3[2*lane+0]*mx + d_c3[2*lane+0];
    ry = d_a3[2*lane+1]*my + d_c3[2*lane+1];
  } else { rx = 0.f; ry = 0.f; }
  ((float2*)(out + (size_t)node*HID))[lane] = make_float2(rx, ry);
}

// ---------------- launch ------------------------------------------------------------
extern "C" void kernel_launch(void* const* d_in, const int* in_sizes, int n_in,
                              void* d_out, int out_size){
  const float*     x   = (const float*)d_in[0];
  const float*     pos = (const float*)d_in[1];
  const void*      ei  = d_in[2];
  const float* W1=(const float*)d_in[3];  const float* b1=(const float*)d_in[4];
  const float* g1=(const float*)d_in[5];  const float* be1=(const float*)d_in[6];
  const float* W2=(const float*)d_in[7];  const float* b2=(const float*)d_in[8];
  const float* g2=(const float*)d_in[9];  const float* be2=(const float*)d_in[10];
  const float* W3=(const float*)d_in[11]; const float* b3=(const float*)d_in[12];
  const float* g3=(const float*)d_in[13]; const float* be3=(const float*)d_in[14];
  float* out = (float*)d_out;
  (void)in_sizes; (void)n_in; (void)out_size;

  k_init<<<128,256>>>();
  k_detect<<<1024,256>>>((const long long*)ei);
  k_cvt_norm_hist<<<2048,256>>>(ei, pos);
  k_scan1<<<NBLK,1024>>>();
  k_scan2<<<1,128>>>();
  k_scan3<<<NBLK,1024>>>();
  k_scatter<<<2048,256>>>();
  k_layer1<<<2048,256>>>(pos, x, W1, b1);
  k_fold<<<1,64>>>(W2, b2, g1, be1, 0);
  k_layer<<<12500,256>>>(0);
  k_fold<<<1,64>>>(W3, b3, g2, be2, 1);
  k_layer<<<12500,256>>>(1);
  k_affine3<<<1,64>>>(g3, be3);
  k_gather<<<12500,256>>>(out);
}

// round 4
// speedup vs baseline: 1.1490x; 1.0090x over previous
#include <cuda_runtime.h>
#include <cuda_fp16.h>

#define E_EDGES 1600000
#define NN 100000
#define HID 64
#define BN_EPS 1e-5f
#define INV_E (1.0f/1600000.0f)
#define NBLK 98   // ceil(NN/1024)

typedef unsigned long long ull;

__device__ __forceinline__ ull pack2(float lo, float hi){
  ull r; asm("mov.b64 %0,{%1,%2};" : "=l"(r) : "f"(lo), "f"(hi)); return r;
}
__device__ __forceinline__ void unpack2(ull v, float &lo, float &hi){
  asm("mov.b64 {%0,%1},%2;" : "=f"(lo), "=f"(hi) : "l"(v));
}
__device__ __forceinline__ ull fma2(ull a, ull b, ull c){
  ull d; asm("fma.rn.f32x2 %0,%1,%2,%3;" : "=l"(d) : "l"(a), "l"(b), "l"(c)); return d;
}

// ---------------- scratch (device globals; no allocations allowed) ----------------
__device__ __half d_h1[(size_t)E_EDGES*HID];   // h1, later reused for h3
__device__ __half d_h2[(size_t)E_EDGES*HID];
__device__ int d_src[E_EDGES], d_dst[E_EDGES];
__device__ float d_sum0[HID], d_sq0[HID];
__device__ float d_sum1[HID], d_sq1[HID];
__device__ float d_sum2[HID], d_sq2[HID];
__device__ float d_normsq;
__device__ int d_is64;
__device__ float d_W2f[HID*HID], d_b2f[HID];
__device__ float d_W3f[HID*HID], d_b3f[HID];
__device__ float d_a3[HID], d_c3[HID];
__device__ int d_cnt[NN], d_off[NN+1], d_cur[NN], d_csr[E_EDGES];
__device__ int d_blk[128];

// ---------------- init: zero counters / stats (must re-run every graph replay) ----
__global__ void k_init(){
  int i = blockIdx.x*blockDim.x + threadIdx.x;
  int stride = gridDim.x*blockDim.x;
  for (int j=i; j<NN; j+=stride) d_cnt[j]=0;
  if (i < HID){
    d_sum0[i]=0.f; d_sq0[i]=0.f;
    d_sum1[i]=0.f; d_sq1[i]=0.f;
    d_sum2[i]=0.f; d_sq2[i]=0.f;
  }
  if (i==0){ d_normsq = 0.f; d_is64 = 1; }
}

// ---------------- dtype probe: int64 vs int32 edge_index ---------------------------
__global__ void k_detect(const long long* __restrict__ ei){
  int tid = blockIdx.x*blockDim.x + threadIdx.x;
  int bad = 0;
  #pragma unroll 4
  for (int i = tid; i < (1<<20); i += gridDim.x*blockDim.x){
    long long v = ei[i];
    if (v < 0 || v >= NN) bad = 1;
  }
  if (__syncthreads_or(bad)){
    if (threadIdx.x == 0) d_is64 = 0;
  }
}

// ---------------- convert indices + global norm + dst histogram --------------------
__global__ void k_cvt_norm_hist(const void* __restrict__ eiv, const float* __restrict__ pos){
  const long long* ei64 = (const long long*)eiv;
  const int*       ei32 = (const int*)eiv;
  const bool is64 = (d_is64 != 0);
  int tid = blockIdx.x*blockDim.x + threadIdx.x;
  int stride = gridDim.x*blockDim.x;
  float local = 0.f;
  for (int e = tid; e < E_EDGES; e += stride){
    int s, d;
    if (is64){ s = (int)ei64[e]; d = (int)ei64[E_EDGES + e]; }
    else     { s = ei32[e];      d = ei32[E_EDGES + e]; }
    d_src[e] = s; d_dst[e] = d;
    float dx = pos[3*s+0] - pos[3*d+0];
    float dy = pos[3*s+1] - pos[3*d+1];
    float dz = pos[3*s+2] - pos[3*d+2];
    local += dx*dx + dy*dy + dz*dz;
    atomicAdd(&d_cnt[d], 1);
  }
  #pragma unroll
  for (int o=16;o>0;o>>=1) local += __shfl_down_sync(0xffffffffu, local, o);
  __shared__ float red[8];
  int lane = threadIdx.x & 31, wid = threadIdx.x >> 5;
  if (lane==0) red[wid]=local;
  __syncthreads();
  if (threadIdx.x==0){
    float s=0.f;
    #pragma unroll
    for (int i=0;i<8;i++) s+=red[i];
    atomicAdd(&d_normsq, s);
  }
}

// ---------------- parallel 3-phase exclusive scan ----------------------------------
__global__ void k_scan1(){
  __shared__ int wsum[32];
  int t = threadIdx.x, lane = t & 31, wid = t >> 5;
  int idx = blockIdx.x*1024 + t;
  int v = (idx < NN) ? d_cnt[idx] : 0;
  int x = v;
  #pragma unroll
  for (int o=1;o<32;o<<=1){ int y=__shfl_up_sync(0xffffffffu,x,o); if(lane>=o) x+=y; }
  if (lane==31) wsum[wid]=x;
  __syncthreads();
  if (wid==0){
    int y = wsum[lane];
    #pragma unroll
    for (int o=1;o<32;o<<=1){ int z=__shfl_up_sync(0xffffffffu,y,o); if(lane>=o) y+=z; }
    wsum[lane]=y;
  }
  __syncthreads();
  int excl = x - v + ((wid>0)? wsum[wid-1] : 0);
  if (idx < NN) d_off[idx] = excl;
  if (t==1023) d_blk[blockIdx.x] = wsum[31];
}

__global__ void k_scan2(){
  __shared__ int wsum[4];
  int t = threadIdx.x, lane = t & 31, wid = t >> 5;   // 128 threads
  int v = (t < NBLK) ? d_blk[t] : 0;
  int x = v;
  #pragma unroll
  for (int o=1;o<32;o<<=1){ int y=__shfl_up_sync(0xffffffffu,x,o); if(lane>=o) x+=y; }
  if (lane==31) wsum[wid]=x;
  __syncthreads();
  int woff = 0;
  for (int w=0; w<wid; w++) woff += wsum[w];
  if (t < NBLK) d_blk[t] = x - v + woff;
}

__global__ void k_scan3(){
  int idx = blockIdx.x*1024 + threadIdx.x;
  if (idx < NN){
    int o = d_off[idx] + d_blk[blockIdx.x];
    d_off[idx] = o; d_cur[idx] = o;
  }
  if (idx == 0) d_off[NN] = E_EDGES;
}

// ---------------- CSR fill --------------------------------------------------------
__global__ void k_scatter(){
  int tid = blockIdx.x*blockDim.x + threadIdx.x;
  int stride = gridDim.x*blockDim.x;
  for (int e=tid; e<E_EDGES; e+=stride){
    int d = d_dst[e];
    int p = atomicAdd(&d_cur[d], 1);
    d_csr[p] = e;
  }
}

// ---------------- layer 1: 6 -> 64, per-edge, lane = channel pair ------------------
__global__ void k_layer1(const float* __restrict__ pos,
                         const float* __restrict__ x, const float* __restrict__ W1,
                         const float* __restrict__ b1){
  int lane = threadIdx.x & 31;
  int gw = (blockIdx.x*blockDim.x + threadIdx.x) >> 5;
  int nw = (gridDim.x*blockDim.x) >> 5;
  float invn = rsqrtf(d_normsq);
  ull wp[6];
  #pragma unroll
  for (int k=0;k<6;k++){
    float2 w = ((const float2*)(W1 + k*HID))[lane];
    wp[k] = pack2(w.x, w.y);
  }
  float2 bb = ((const float2*)b1)[lane];
  ull bias = pack2(bb.x, bb.y);
  float sx=0.f, sy=0.f, qx=0.f, qy=0.f;
  for (int e=gw; e<E_EDGES; e+=nw){
    int s = d_src[e];
    int d = d_dst[e];
    float i0 = (pos[3*s+0]-pos[3*d+0])*invn;
    float i1 = (pos[3*s+1]-pos[3*d+1])*invn;
    float i2 = (pos[3*s+2]-pos[3*d+2])*invn;
    float i3 = x[3*d+0], i4 = x[3*d+1], i5 = x[3*d+2];
    ull acc = bias;
    acc = fma2(pack2(i0,i0), wp[0], acc);
    acc = fma2(pack2(i1,i1), wp[1], acc);
    acc = fma2(pack2(i2,i2), wp[2], acc);
    acc = fma2(pack2(i3,i3), wp[3], acc);
    acc = fma2(pack2(i4,i4), wp[4], acc);
    acc = fma2(pack2(i5,i5), wp[5], acc);
    float h0, h1v; unpack2(acc, h0, h1v);
    h0 = fmaxf(h0, 0.f); h1v = fmaxf(h1v, 0.f);
    ((__half2*)(d_h1 + (size_t)e*HID))[lane] = __floats2half2_rn(h0, h1v);
    sx += h0; sy += h1v; qx += h0*h0; qy += h1v*h1v;
  }
  atomicAdd(&d_sum0[2*lane+0], sx);
  atomicAdd(&d_sum0[2*lane+1], sy);
  atomicAdd(&d_sq0 [2*lane+0], qx);
  atomicAdd(&d_sq0 [2*lane+1], qy);
}

// ---------------- fold BN(prev layer) into next layer's weights -------------------
__global__ void k_fold(const float* __restrict__ W, const float* __restrict__ b,
                       const float* __restrict__ g, const float* __restrict__ be, int which){
  __shared__ float a[HID], c[HID];
  int t = threadIdx.x;
  const float* sum = (which==0) ? d_sum0 : d_sum1;
  const float* sq  = (which==0) ? d_sq0  : d_sq1;
  float* Wf = (which==0) ? d_W2f : d_W3f;
  float* bf = (which==0) ? d_b2f : d_b3f;
  float mu = sum[t]*INV_E;
  float var = sq[t]*INV_E - mu*mu;
  float av = g[t]*rsqrtf(var + BN_EPS);
  a[t] = av; c[t] = be[t] - av*mu;
  __syncthreads();
  float cb = 0.f;
  for (int k=0;k<HID;k++){
    float w = W[k*HID + t];
    Wf[k*HID + t] = a[k]*w;
    cb += c[k]*w;
  }
  bf[t] = b[t] + cb;
}

__global__ void k_affine3(const float* __restrict__ g, const float* __restrict__ be){
  int t = threadIdx.x;
  float mu = d_sum2[t]*INV_E;
  float var = d_sq2[t]*INV_E - mu*mu;
  float av = g[t]*rsqrtf(var + BN_EPS);
  d_a3[t] = av; d_c3[t] = be[t] - av*mu;
}

// ---------------- layer 2/3: 64x64 GEMM + relu + stats, f32x2 packed FMA -----------
__global__ void __launch_bounds__(256) k_layer(int which){
  const __half* __restrict__ hin = (which==0) ? d_h1 : d_h2;
  __half* __restrict__ hout      = (which==0) ? d_h2 : d_h1;
  const float* __restrict__ Wf   = (which==0) ? d_W2f : d_W3f;
  const float* __restrict__ bf   = (which==0) ? d_b2f : d_b3f;
  float* gs = (which==0) ? d_sum1 : d_sum2;
  float* gq = (which==0) ? d_sq1  : d_sq2;

  __shared__ float Ash[128][65];
  __shared__ float Wsh[64][64];
  __shared__ float bsh[64];
  __shared__ float ssum[64], ssq[64];

  int t = threadIdx.x;
  size_t e0 = (size_t)blockIdx.x * 128;

  {
    const float4* W4 = (const float4*)Wf;
    float4* Wd = (float4*)&Wsh[0][0];
    #pragma unroll
    for (int i=0;i<4;i++) Wd[t + 256*i] = W4[t + 256*i];
  }
  if (t < 64){ bsh[t] = bf[t]; ssum[t]=0.f; ssq[t]=0.f; }
  {
    // 128 edges x 64 ch halves = 16KB = 1024 uint4; thread handles 4
    const uint4* h4 = (const uint4*)(hin + e0*HID);
    #pragma unroll
    for (int i=0;i<4;i++){
      int idx = t + 256*i;           // uint4 index; edge = idx>>3, chunk = idx&7
      uint4 v = h4[idx];
      int e = idx >> 3;
      int c8 = (idx & 7) << 3;
      const __half2* hp = (const __half2*)&v;
      #pragma unroll
      for (int j=0;j<4;j++){
        float2 f = __half22float2(hp[j]);
        Ash[e][c8 + 2*j + 0] = f.x;
        Ash[e][c8 + 2*j + 1] = f.y;
      }
    }
  }
  __syncthreads();

  int cg = t & 7;        // channel group (8 channels = 4 pairs)
  int eg = t >> 3;       // edge group (4 edges)
  int ebase = eg << 2;
  int cbase = cg << 3;

  ull acc[4][4];
  {
    ull b0 = pack2(bsh[cbase+0], bsh[cbase+1]);
    ull b1v= pack2(bsh[cbase+2], bsh[cbase+3]);
    ull b2v= pack2(bsh[cbase+4], bsh[cbase+5]);
    ull b3v= pack2(bsh[cbase+6], bsh[cbase+7]);
    #pragma unroll
    for (int i=0;i<4;i++){ acc[i][0]=b0; acc[i][1]=b1v; acc[i][2]=b2v; acc[i][3]=b3v; }
  }

  #pragma unroll 8
  for (int k=0;k<64;k++){
    const ull* wr = (const ull*)&Wsh[k][cbase];
    ull w0=wr[0], w1=wr[1], w2=wr[2], w3=wr[3];
    #pragma unroll
    for (int i=0;i<4;i++){
      float a = Ash[ebase+i][k];
      ull aa = pack2(a,a);
      acc[i][0] = fma2(aa, w0, acc[i][0]);
      acc[i][1] = fma2(aa, w1, acc[i][1]);
      acc[i][2] = fma2(aa, w2, acc[i][2]);
      acc[i][3] = fma2(aa, w3, acc[i][3]);
    }
  }

  float2 s[4], q[4];
  #pragma unroll
  for (int j=0;j<4;j++){ s[j]=make_float2(0.f,0.f); q[j]=make_float2(0.f,0.f); }

  #pragma unroll
  for (int i=0;i<4;i++){
    float v[8];
    unpack2(acc[i][0], v[0], v[1]);
    unpack2(acc[i][1], v[2], v[3]);
    unpack2(acc[i][2], v[4], v[5]);
    unpack2(acc[i][3], v[6], v[7]);
    #pragma unroll
    for (int m=0;m<8;m++) v[m] = fmaxf(v[m], 0.f);
    // pack 8 halves = uint4, store 16B
    uint4 ov;
    __half2* op = (__half2*)&ov;
    op[0] = __floats2half2_rn(v[0], v[1]);
    op[1] = __floats2half2_rn(v[2], v[3]);
    op[2] = __floats2half2_rn(v[4], v[5]);
    op[3] = __floats2half2_rn(v[6], v[7]);
    *(uint4*)(hout + (e0 + (size_t)(ebase + i))*HID + cbase) = ov;
    #pragma unroll
    for (int j=0;j<4;j++){
      s[j].x += v[2*j]; s[j].y += v[2*j+1];
      q[j].x += v[2*j]*v[2*j]; q[j].y += v[2*j+1]*v[2*j+1];
    }
  }

  #pragma unroll
  for (int j=0;j<4;j++){
    atomicAdd(&ssum[cbase+2*j+0], s[j].x);
    atomicAdd(&ssum[cbase+2*j+1], s[j].y);
    atomicAdd(&ssq [cbase+2*j+0], q[j].x);
    atomicAdd(&ssq [cbase+2*j+1], q[j].y);
  }
  __syncthreads();
  if (t < 64){
    atomicAdd(&gs[t], ssum[t]);
    atomicAdd(&gq[t], ssq[t]);
  }
}

// ---------------- per-node gather max + BN3 affine ---------------------------------
__global__ void k_gather(float* __restrict__ out){
  int lane = threadIdx.x & 31;
  int node = (blockIdx.x*blockDim.x + threadIdx.x) >> 5;
  if (node >= NN) return;
  int beg = d_off[node], end = d_off[node+1];
  float mx = -3.402823466e38f, my = -3.402823466e38f;
  for (int base=beg; base<end; base+=32){
    int p = base + lane;
    int eL = (p < end) ? d_csr[p] : 0;
    int cnt = min(32, end - base);
    for (int j=0;j<cnt;j++){
      int e = __shfl_sync(0xffffffffu, eL, j);
      float2 v = __half22float2(((const __half2*)(d_h1 + (size_t)e*HID))[lane]);
      mx = fmaxf(mx, v.x); my = fmaxf(my, v.y);
    }
  }
  float rx, ry;
  if (end > beg){
    rx = d_a3[2*lane+0]*mx + d_c3[2*lane+0];
    ry = d_a3[2*lane+1]*my + d_c3[2*lane+1];
  } else { rx = 0.f; ry = 0.f; }
  ((float2*)(out + (size_t)node*HID))[lane] = make_float2(rx, ry);
}

// ---------------- launch ------------------------------------------------------------
extern "C" void kernel_launch(void* const* d_in, const int* in_sizes, int n_in,
                              void* d_out, int out_size){
  const float*     x   = (const float*)d_in[0];
  const float*     pos = (const float*)d_in[1];
  const void*      ei  = d_in[2];
  const float* W1=(const float*)d_in[3];  const float* b1=(const float*)d_in[4];
  const float* g1=(const float*)d_in[5];  const float* be1=(const float*)d_in[6];
  const float* W2=(const float*)d_in[7];  const float* b2=(const float*)d_in[8];
  const float* g2=(const float*)d_in[9];  const float* be2=(const float*)d_in[10];
  const float* W3=(const float*)d_in[11]; const float* b3=(const float*)d_in[12];
  const float* g3=(const float*)d_in[13]; const float* be3=(const float*)d_in[14];
  float* out = (float*)d_out;
  (void)in_sizes; (void)n_in; (void)out_size;

  k_init<<<128,256>>>();
  k_detect<<<1024,256>>>((const long long*)ei);
  k_cvt_norm_hist<<<2048,256>>>(ei, pos);
  k_scan1<<<NBLK,1024>>>();
  k_scan2<<<1,128>>>();
  k_scan3<<<NBLK,1024>>>();
  k_scatter<<<2048,256>>>();
  k_layer1<<<2048,256>>>(pos, x, W1, b1);
  k_fold<<<1,64>>>(W2, b2, g1, be1, 0);
  k_layer<<<12500,256>>>(0);
  k_fold<<<1,64>>>(W3, b3, g2, be2, 1);
  k_layer<<<12500,256>>>(1);
  k_affine3<<<1,64>>>(g3, be3);
  k_gather<<<12500,256>>>(out);
}